// round 1
// baseline (speedup 1.0000x reference)
#include <cuda_runtime.h>
#include <cstdint>

// Problem constants
#define N_TOK 8192
#define C_DIM 1024
#define F_DIM 4096
#define E_NUM 8
#define S_SLOTS (N_TOK * 2)
#define CAP 2048

// ---------------- scratch (static device globals; no allocation allowed) ----
__device__ float g_disp[(size_t)E_NUM * CAP * C_DIM];   // 64 MB
__device__ float g_h[(size_t)E_NUM * CAP * F_DIM];      // 256 MB
__device__ float g_y[(size_t)E_NUM * CAP * C_DIM];      // 64 MB
__device__ int   g_eidx[S_SLOTS];
__device__ float g_wf[S_SLOTS];
__device__ int   g_loc[S_SLOTS];
__device__ float g_probs_sum[E_NUM];

// ---------------- helpers ----------------------------------------------------
__device__ __forceinline__ float gelu_tanh(float x) {
    const float k0 = 0.7978845608028654f;   // sqrt(2/pi)
    float x3 = x * x * x;
    float t = tanhf(k0 * (x + 0.044715f * x3));
    return 0.5f * x * (1.0f + t);
}

__device__ __forceinline__ float to_tf32(float x) {
    uint32_t u;
    asm("cvt.rna.tf32.f32 %0, %1;" : "=r"(u) : "f"(x));
    return __uint_as_float(u);
}

__device__ __forceinline__ void mma_tf32(float* d, const uint32_t* a, const uint32_t* b) {
    asm volatile(
        "mma.sync.aligned.m16n8k8.row.col.f32.tf32.tf32.f32 "
        "{%0,%1,%2,%3}, {%4,%5,%6,%7}, {%8,%9}, {%0,%1,%2,%3};"
        : "+f"(d[0]), "+f"(d[1]), "+f"(d[2]), "+f"(d[3])
        : "r"(a[0]), "r"(a[1]), "r"(a[2]), "r"(a[3]), "r"(b[0]), "r"(b[1]));
}

// ---------------- init -------------------------------------------------------
__global__ void init_kernel() {
    int t = threadIdx.x;
    if (t < E_NUM) g_probs_sum[t] = 0.0f;
}

// ---------------- gating: logits -> softmax -> top2 --------------------------
// 1024 blocks x 256 threads; one warp per token.
__global__ void gate_kernel(const float* __restrict__ x,
                            const float* __restrict__ w_gate,
                            const float* __restrict__ b_gate) {
    __shared__ float sprob[E_NUM];
    int tid = threadIdx.x;
    if (tid < E_NUM) sprob[tid] = 0.0f;
    __syncthreads();

    int warp = tid >> 5, lane = tid & 31;
    int n = blockIdx.x * 8 + warp;
    const float* xr = x + (size_t)n * C_DIM;

    float acc[E_NUM];
#pragma unroll
    for (int e = 0; e < E_NUM; e++) acc[e] = 0.0f;

    for (int c = lane; c < C_DIM; c += 32) {
        float xv = xr[c];
        const float4* w4 = (const float4*)(w_gate + (size_t)c * E_NUM);
        float4 wa = w4[0], wb = w4[1];
        acc[0] += xv * wa.x; acc[1] += xv * wa.y;
        acc[2] += xv * wa.z; acc[3] += xv * wa.w;
        acc[4] += xv * wb.x; acc[5] += xv * wb.y;
        acc[6] += xv * wb.z; acc[7] += xv * wb.w;
    }
#pragma unroll
    for (int e = 0; e < E_NUM; e++)
#pragma unroll
        for (int o = 16; o > 0; o >>= 1)
            acc[e] += __shfl_down_sync(0xffffffffu, acc[e], o);

    if (lane == 0) {
        float p[E_NUM];
        float mx = -1e30f;
#pragma unroll
        for (int e = 0; e < E_NUM; e++) {
            p[e] = acc[e] + b_gate[e];
            mx = fmaxf(mx, p[e]);
        }
        float s = 0.0f;
#pragma unroll
        for (int e = 0; e < E_NUM; e++) { p[e] = expf(p[e] - mx); s += p[e]; }
        float inv = 1.0f / s;
#pragma unroll
        for (int e = 0; e < E_NUM; e++) p[e] *= inv;

        // top-2 (ties -> lower index first, matching lax.top_k)
        int i0 = 0;
#pragma unroll
        for (int e = 1; e < E_NUM; e++) if (p[e] > p[i0]) i0 = e;
        int i1 = (i0 == 0) ? 1 : 0;
#pragma unroll
        for (int e = 0; e < E_NUM; e++) if (e != i0 && p[e] > p[i1]) i1 = e;

        float w0 = p[i0], w1 = p[i1];
        float ws = w0 + w1 + 1e-9f;
        g_eidx[2 * n]     = i0;
        g_eidx[2 * n + 1] = i1;
        g_wf[2 * n]       = w0 / ws;
        g_wf[2 * n + 1]   = w1 / ws;
#pragma unroll
        for (int e = 0; e < E_NUM; e++) atomicAdd(&sprob[e], p[e]);
    }
    __syncthreads();
    if (tid < E_NUM) atomicAdd(&g_probs_sum[tid], sprob[tid]);
}

// ---------------- FCFS capacity scan + aux loss -------------------------------
// Single block, 256 threads, 64 slots each. Per-expert counts packed 16b x 4
// into two u64s; Hillis-Steele exclusive scan reproduces slot-order cumsum.
__global__ void scan_kernel(float* __restrict__ d_out, int out_size) {
    const int PER = 64;
    int t = threadIdx.x;
    int base = t * PER;

    int cnt[E_NUM];
#pragma unroll
    for (int e = 0; e < E_NUM; e++) cnt[e] = 0;
    for (int i = 0; i < PER; i++) cnt[g_eidx[base + i]]++;

    unsigned long long lo = 0, hi = 0;
#pragma unroll
    for (int e = 0; e < 4; e++) {
        lo |= (unsigned long long)cnt[e] << (16 * e);
        hi |= (unsigned long long)cnt[e + 4] << (16 * e);
    }

    __shared__ unsigned long long s0[256], s1[256];
    s0[t] = lo; s1[t] = hi;
    __syncthreads();
    for (int off = 1; off < 256; off <<= 1) {
        unsigned long long v0 = 0, v1 = 0;
        if (t >= off) { v0 = s0[t - off]; v1 = s1[t - off]; }
        __syncthreads();
        s0[t] += v0; s1[t] += v1;
        __syncthreads();
    }
    unsigned long long p0 = (t > 0) ? s0[t - 1] : 0ULL;
    unsigned long long p1 = (t > 0) ? s1[t - 1] : 0ULL;

    int exc[E_NUM];
#pragma unroll
    for (int e = 0; e < 4; e++) {
        exc[e]     = (int)((p0 >> (16 * e)) & 0xffffULL);
        exc[e + 4] = (int)((p1 >> (16 * e)) & 0xffffULL);
    }
    for (int i = 0; i < PER; i++) {
        int s = base + i;
        int e = g_eidx[s];
        int pos = exc[e]++;
        g_loc[s] = (pos < CAP) ? (e * CAP + pos) : -1;
    }

    if (t == 0) {
        unsigned long long t0 = s0[255], t1 = s1[255];
        float sumload = 0.0f, load[E_NUM];
#pragma unroll
        for (int e = 0; e < 4; e++) {
            int c0 = (int)((t0 >> (16 * e)) & 0xffffULL);
            int c1 = (int)((t1 >> (16 * e)) & 0xffffULL);
            load[e]     = (float)min(c0, CAP);
            load[e + 4] = (float)min(c1, CAP);
        }
#pragma unroll
        for (int e = 0; e < E_NUM; e++) sumload += load[e];
        float fe[E_NUM], sfe = 0.0f;
#pragma unroll
        for (int e = 0; e < E_NUM; e++) { fe[e] = g_probs_sum[e] / (float)N_TOK; sfe += fe[e]; }
        float aux = 0.0f;
#pragma unroll
        for (int e = 0; e < E_NUM; e++) {
            float fn = fe[e] / (sfe + 1e-9f);
            float fa = load[e] / (sumload + 1e-9f);
            float d = fn - fa;
            aux += d * d;
        }
        aux = 0.01f * aux / (float)E_NUM;
        if (out_size > N_TOK * C_DIM)
            d_out[(size_t)N_TOK * C_DIM] = aux;
    }
}

// ---------------- dispatch gather (only kept slots; no zero-fill needed) -----
__global__ void dispatch_kernel(const float* __restrict__ x) {
    int s = blockIdx.x;
    int loc = g_loc[s];
    if (loc < 0) return;
    const float4* src = (const float4*)(x + ((size_t)(s >> 1)) * C_DIM);
    float4* dst = (float4*)(g_disp + (size_t)loc * C_DIM);
    int t = threadIdx.x;  // 128
    dst[t] = src[t];
    dst[t + 128] = src[t + 128];
}

// ---------------- grouped GEMM: TF32 mma.sync, 128x128x32 tiles --------------
// A: [E*M][K] row-major, W: [E][K][N] row-major, bias [E][N], Out [E*M][N].
template <bool GELU>
__global__ __launch_bounds__(256)
void gemm_kernel(const float* __restrict__ A, const float* __restrict__ W,
                 const float* __restrict__ bias, float* __restrict__ Out,
                 int M, int N, int Kd) {
    const int BM = 128, BN = 128, BK = 32;
    int e = blockIdx.z;
    int bm = blockIdx.y, bn = blockIdx.x;
    const float* Ae = A + (size_t)e * M * Kd;
    const float* We = W + (size_t)e * Kd * N;
    float* Oe = Out + (size_t)e * M * N;

    __shared__ float As[BM][36];        // padded
    __shared__ float Bs[BK][BN + 4];

    int tid = threadIdx.x;
    int warp = tid >> 5, lane = tid & 31;
    int g = lane >> 2, tig = lane & 3;
    int wm = warp >> 2;  // 0..1, 64 rows each
    int wn = warp & 3;   // 0..3, 32 cols each

    float acc[4][4][4];
#pragma unroll
    for (int i = 0; i < 4; i++)
#pragma unroll
        for (int j = 0; j < 4; j++)
#pragma unroll
            for (int k = 0; k < 4; k++) acc[i][j][k] = 0.0f;

    int a_row = tid >> 3;          // 0..31
    int a_col = (tid & 7) * 4;     // 0..28
    int b_row = tid >> 5;          // 0..7
    int b_col = (tid & 31) * 4;    // 0..124

    for (int k0 = 0; k0 < Kd; k0 += BK) {
#pragma unroll
        for (int p = 0; p < 4; p++) {
            int r = a_row + p * 32;
            float4 v = *(const float4*)(Ae + (size_t)(bm * BM + r) * Kd + k0 + a_col);
            As[r][a_col + 0] = to_tf32(v.x);
            As[r][a_col + 1] = to_tf32(v.y);
            As[r][a_col + 2] = to_tf32(v.z);
            As[r][a_col + 3] = to_tf32(v.w);
        }
#pragma unroll
        for (int p = 0; p < 4; p++) {
            int r = b_row + p * 8;
            float4 v = *(const float4*)(We + (size_t)(k0 + r) * N + bn * BN + b_col);
            Bs[r][b_col + 0] = to_tf32(v.x);
            Bs[r][b_col + 1] = to_tf32(v.y);
            Bs[r][b_col + 2] = to_tf32(v.z);
            Bs[r][b_col + 3] = to_tf32(v.w);
        }
        __syncthreads();

#pragma unroll
        for (int kk = 0; kk < 4; kk++) {
            int kb = kk * 8;
            uint32_t af[4][4];
#pragma unroll
            for (int mt = 0; mt < 4; mt++) {
                int r0 = wm * 64 + mt * 16 + g;
                af[mt][0] = __float_as_uint(As[r0][kb + tig]);
                af[mt][1] = __float_as_uint(As[r0 + 8][kb + tig]);
                af[mt][2] = __float_as_uint(As[r0][kb + tig + 4]);
                af[mt][3] = __float_as_uint(As[r0 + 8][kb + tig + 4]);
            }
            uint32_t bf[4][2];
#pragma unroll
            for (int nt = 0; nt < 4; nt++) {
                int c0 = wn * 32 + nt * 8 + g;
                bf[nt][0] = __float_as_uint(Bs[kb + tig][c0]);
                bf[nt][1] = __float_as_uint(Bs[kb + tig + 4][c0]);
            }
#pragma unroll
            for (int mt = 0; mt < 4; mt++)
#pragma unroll
                for (int nt = 0; nt < 4; nt++)
                    mma_tf32(acc[mt][nt], af[mt], bf[nt]);
        }
        __syncthreads();
    }

    // epilogue
#pragma unroll
    for (int mt = 0; mt < 4; mt++) {
        int r0 = bm * BM + wm * 64 + mt * 16 + g;
#pragma unroll
        for (int nt = 0; nt < 4; nt++) {
            int c0 = bn * BN + wn * 32 + nt * 8 + 2 * tig;
            float bv0 = bias[(size_t)e * N + c0];
            float bv1 = bias[(size_t)e * N + c0 + 1];
            float v00 = acc[mt][nt][0] + bv0;
            float v01 = acc[mt][nt][1] + bv1;
            float v10 = acc[mt][nt][2] + bv0;
            float v11 = acc[mt][nt][3] + bv1;
            if (GELU) {
                v00 = gelu_tanh(v00); v01 = gelu_tanh(v01);
                v10 = gelu_tanh(v10); v11 = gelu_tanh(v11);
            }
            float2 o0 = make_float2(v00, v01);
            float2 o1 = make_float2(v10, v11);
            *(float2*)(Oe + (size_t)r0 * N + c0) = o0;
            *(float2*)(Oe + (size_t)(r0 + 8) * N + c0) = o1;
        }
    }
}

// ---------------- combine gather ---------------------------------------------
__global__ void combine_kernel(float* __restrict__ out) {
    int n = blockIdx.x;
    int l0 = g_loc[2 * n], l1 = g_loc[2 * n + 1];
    float w0 = (l0 >= 0) ? g_wf[2 * n] : 0.0f;
    float w1 = (l1 >= 0) ? g_wf[2 * n + 1] : 0.0f;
    const float4* y0 = (const float4*)(g_y + (size_t)max(l0, 0) * C_DIM);
    const float4* y1 = (const float4*)(g_y + (size_t)max(l1, 0) * C_DIM);
    float4* dst = (float4*)(out + (size_t)n * C_DIM);
    int t = threadIdx.x;  // 128
#pragma unroll
    for (int j = 0; j < 2; j++) {
        int idx = t + j * 128;
        float4 a = (l0 >= 0) ? y0[idx] : make_float4(0, 0, 0, 0);
        float4 b = (l1 >= 0) ? y1[idx] : make_float4(0, 0, 0, 0);
        float4 r;
        r.x = w0 * a.x + w1 * b.x;
        r.y = w0 * a.y + w1 * b.y;
        r.z = w0 * a.z + w1 * b.z;
        r.w = w0 * a.w + w1 * b.w;
        dst[idx] = r;
    }
}

// ---------------- launcher ----------------------------------------------------
extern "C" void kernel_launch(void* const* d_in, const int* in_sizes, int n_in,
                              void* d_out, int out_size) {
    const float* x      = (const float*)d_in[0];
    const float* w_gate = (const float*)d_in[1];
    const float* b_gate = (const float*)d_in[2];
    const float* W1     = (const float*)d_in[3];
    const float* b1     = (const float*)d_in[4];
    const float* W2     = (const float*)d_in[5];
    const float* b2     = (const float*)d_in[6];
    float* out = (float*)d_out;

    init_kernel<<<1, 32>>>();
    gate_kernel<<<N_TOK / 8, 256>>>(x, w_gate, b_gate);
    scan_kernel<<<1, 256>>>(out, out_size);
    dispatch_kernel<<<S_SLOTS, 128>>>(x);

    {
        float* disp = nullptr; float* h = nullptr;
        cudaGetSymbolAddress((void**)&disp, g_disp);
        cudaGetSymbolAddress((void**)&h, g_h);
        dim3 grid1(F_DIM / 128, CAP / 128, E_NUM);
        gemm_kernel<true><<<grid1, 256>>>(disp, W1, b1, h, CAP, F_DIM, C_DIM);

        float* y = nullptr;
        cudaGetSymbolAddress((void**)&y, g_y);
        dim3 grid2(C_DIM / 128, CAP / 128, E_NUM);
        gemm_kernel<false><<<grid2, 256>>>(h, W2, b2, y, CAP, C_DIM, F_DIM);
    }

    combine_kernel<<<N_TOK, 128>>>(out);
}

// round 2
// speedup vs baseline: 1.0989x; 1.0989x over previous
#include <cuda_runtime.h>
#include <cstdint>

// Problem constants
#define N_TOK 8192
#define C_DIM 1024
#define F_DIM 4096
#define E_NUM 8
#define S_SLOTS (N_TOK * 2)
#define CAP 2048

// ---------------- scratch (static device globals; no allocation allowed) ----
__device__ float g_disp[(size_t)E_NUM * CAP * C_DIM];   // 64 MB (tf32-rounded)
__device__ float g_h[(size_t)E_NUM * CAP * F_DIM];      // 256 MB (tf32-rounded)
__device__ float g_y[(size_t)E_NUM * CAP * C_DIM];      // 64 MB
__device__ float g_W1t[(size_t)E_NUM * C_DIM * F_DIM];  // 134 MB (tf32-rounded W1)
__device__ float g_W2t[(size_t)E_NUM * F_DIM * C_DIM];  // 134 MB (tf32-rounded W2)
__device__ int   g_eidx[S_SLOTS];
__device__ float g_wf[S_SLOTS];
__device__ int   g_loc[S_SLOTS];
__device__ float g_probs_sum[E_NUM];

// ---------------- helpers ----------------------------------------------------
__device__ __forceinline__ float gelu_tanh(float x) {
    const float k0 = 0.7978845608028654f;   // sqrt(2/pi)
    float x3 = x * x * x;
    float t = tanhf(k0 * (x + 0.044715f * x3));
    return 0.5f * x * (1.0f + t);
}

__device__ __forceinline__ float to_tf32(float x) {
    uint32_t u;
    asm("cvt.rna.tf32.f32 %0, %1;" : "=r"(u) : "f"(x));
    return __uint_as_float(u);
}

__device__ __forceinline__ void mma_tf32(float* d, const uint32_t* a, const uint32_t* b) {
    asm volatile(
        "mma.sync.aligned.m16n8k8.row.col.f32.tf32.tf32.f32 "
        "{%0,%1,%2,%3}, {%4,%5,%6,%7}, {%8,%9}, {%0,%1,%2,%3};"
        : "+f"(d[0]), "+f"(d[1]), "+f"(d[2]), "+f"(d[3])
        : "r"(a[0]), "r"(a[1]), "r"(a[2]), "r"(a[3]), "r"(b[0]), "r"(b[1]));
}

__device__ __forceinline__ void cp_async16(uint32_t smem_dst, const void* gmem_src) {
    asm volatile("cp.async.cg.shared.global [%0], [%1], 16;\n" :: "r"(smem_dst), "l"(gmem_src));
}
__device__ __forceinline__ void cp_commit() {
    asm volatile("cp.async.commit_group;\n");
}
template <int N>
__device__ __forceinline__ void cp_wait() {
    asm volatile("cp.async.wait_group %0;\n" :: "n"(N));
}

// ---------------- init -------------------------------------------------------
__global__ void init_kernel() {
    int t = threadIdx.x;
    if (t < E_NUM) g_probs_sum[t] = 0.0f;
}

// ---------------- weight rounding (tf32, once per launch) ---------------------
__global__ void round_kernel(const float* __restrict__ src, float* __restrict__ dst, int n4) {
    int i = blockIdx.x * blockDim.x + threadIdx.x;
    if (i >= n4) return;
    float4 v = ((const float4*)src)[i];
    v.x = to_tf32(v.x); v.y = to_tf32(v.y);
    v.z = to_tf32(v.z); v.w = to_tf32(v.w);
    ((float4*)dst)[i] = v;
}

// ---------------- gating: logits -> softmax -> top2 --------------------------
__global__ void gate_kernel(const float* __restrict__ x,
                            const float* __restrict__ w_gate,
                            const float* __restrict__ b_gate) {
    __shared__ float sprob[E_NUM];
    int tid = threadIdx.x;
    if (tid < E_NUM) sprob[tid] = 0.0f;
    __syncthreads();

    int warp = tid >> 5, lane = tid & 31;
    int n = blockIdx.x * 8 + warp;
    const float* xr = x + (size_t)n * C_DIM;

    float acc[E_NUM];
#pragma unroll
    for (int e = 0; e < E_NUM; e++) acc[e] = 0.0f;

    for (int c = lane; c < C_DIM; c += 32) {
        float xv = xr[c];
        const float4* w4 = (const float4*)(w_gate + (size_t)c * E_NUM);
        float4 wa = w4[0], wb = w4[1];
        acc[0] += xv * wa.x; acc[1] += xv * wa.y;
        acc[2] += xv * wa.z; acc[3] += xv * wa.w;
        acc[4] += xv * wb.x; acc[5] += xv * wb.y;
        acc[6] += xv * wb.z; acc[7] += xv * wb.w;
    }
#pragma unroll
    for (int e = 0; e < E_NUM; e++)
#pragma unroll
        for (int o = 16; o > 0; o >>= 1)
            acc[e] += __shfl_down_sync(0xffffffffu, acc[e], o);

    if (lane == 0) {
        float p[E_NUM];
        float mx = -1e30f;
#pragma unroll
        for (int e = 0; e < E_NUM; e++) {
            p[e] = acc[e] + b_gate[e];
            mx = fmaxf(mx, p[e]);
        }
        float s = 0.0f;
#pragma unroll
        for (int e = 0; e < E_NUM; e++) { p[e] = expf(p[e] - mx); s += p[e]; }
        float inv = 1.0f / s;
#pragma unroll
        for (int e = 0; e < E_NUM; e++) p[e] *= inv;

        int i0 = 0;
#pragma unroll
        for (int e = 1; e < E_NUM; e++) if (p[e] > p[i0]) i0 = e;
        int i1 = (i0 == 0) ? 1 : 0;
#pragma unroll
        for (int e = 0; e < E_NUM; e++) if (e != i0 && p[e] > p[i1]) i1 = e;

        float w0 = p[i0], w1 = p[i1];
        float ws = w0 + w1 + 1e-9f;
        g_eidx[2 * n]     = i0;
        g_eidx[2 * n + 1] = i1;
        g_wf[2 * n]       = w0 / ws;
        g_wf[2 * n + 1]   = w1 / ws;
#pragma unroll
        for (int e = 0; e < E_NUM; e++) atomicAdd(&sprob[e], p[e]);
    }
    __syncthreads();
    if (tid < E_NUM) atomicAdd(&g_probs_sum[tid], sprob[tid]);
}

// ---------------- FCFS capacity scan + aux loss -------------------------------
__global__ void scan_kernel(float* __restrict__ d_out, int out_size) {
    const int PER = 64;
    int t = threadIdx.x;
    int base = t * PER;

    int cnt[E_NUM];
#pragma unroll
    for (int e = 0; e < E_NUM; e++) cnt[e] = 0;
    for (int i = 0; i < PER; i++) cnt[g_eidx[base + i]]++;

    unsigned long long lo = 0, hi = 0;
#pragma unroll
    for (int e = 0; e < 4; e++) {
        lo |= (unsigned long long)cnt[e] << (16 * e);
        hi |= (unsigned long long)cnt[e + 4] << (16 * e);
    }

    __shared__ unsigned long long s0[256], s1[256];
    s0[t] = lo; s1[t] = hi;
    __syncthreads();
    for (int off = 1; off < 256; off <<= 1) {
        unsigned long long v0 = 0, v1 = 0;
        if (t >= off) { v0 = s0[t - off]; v1 = s1[t - off]; }
        __syncthreads();
        s0[t] += v0; s1[t] += v1;
        __syncthreads();
    }
    unsigned long long p0 = (t > 0) ? s0[t - 1] : 0ULL;
    unsigned long long p1 = (t > 0) ? s1[t - 1] : 0ULL;

    int exc[E_NUM];
#pragma unroll
    for (int e = 0; e < 4; e++) {
        exc[e]     = (int)((p0 >> (16 * e)) & 0xffffULL);
        exc[e + 4] = (int)((p1 >> (16 * e)) & 0xffffULL);
    }
    for (int i = 0; i < PER; i++) {
        int s = base + i;
        int e = g_eidx[s];
        int pos = exc[e]++;
        g_loc[s] = (pos < CAP) ? (e * CAP + pos) : -1;
    }

    if (t == 0) {
        unsigned long long t0 = s0[255], t1 = s1[255];
        float sumload = 0.0f, load[E_NUM];
#pragma unroll
        for (int e = 0; e < 4; e++) {
            int c0 = (int)((t0 >> (16 * e)) & 0xffffULL);
            int c1 = (int)((t1 >> (16 * e)) & 0xffffULL);
            load[e]     = (float)min(c0, CAP);
            load[e + 4] = (float)min(c1, CAP);
        }
#pragma unroll
        for (int e = 0; e < E_NUM; e++) sumload += load[e];
        float fe[E_NUM], sfe = 0.0f;
#pragma unroll
        for (int e = 0; e < E_NUM; e++) { fe[e] = g_probs_sum[e] / (float)N_TOK; sfe += fe[e]; }
        float aux = 0.0f;
#pragma unroll
        for (int e = 0; e < E_NUM; e++) {
            float fn = fe[e] / (sfe + 1e-9f);
            float fa = load[e] / (sumload + 1e-9f);
            float d = fn - fa;
            aux += d * d;
        }
        aux = 0.01f * aux / (float)E_NUM;
        if (out_size > N_TOK * C_DIM)
            d_out[(size_t)N_TOK * C_DIM] = aux;
    }
}

// ---------------- dispatch gather (tf32-rounded at write) ---------------------
__global__ void dispatch_kernel(const float* __restrict__ x) {
    int s = blockIdx.x;
    int loc = g_loc[s];
    if (loc < 0) return;
    const float4* src = (const float4*)(x + ((size_t)(s >> 1)) * C_DIM);
    float4* dst = (float4*)(g_disp + (size_t)loc * C_DIM);
    int t = threadIdx.x;  // 128
#pragma unroll
    for (int j = 0; j < 2; j++) {
        float4 v = src[t + j * 128];
        v.x = to_tf32(v.x); v.y = to_tf32(v.y);
        v.z = to_tf32(v.z); v.w = to_tf32(v.w);
        dst[t + j * 128] = v;
    }
}

// ---------------- grouped GEMM: TF32 mma.sync, 3-stage cp.async pipeline -----
// A: [E*M][K] row-major (already tf32-rounded), W: [E][K][N] row-major (rounded),
// bias [E][N], Out [E*M][N]. Tiles: 128x128x32, 256 threads, 8 warps.
#define GBM 128
#define GBN 128
#define GBK 32
#define GSTAGES 3
#define A_LD 36
#define B_LD 132
#define ASZ (GBM * A_LD)
#define BSZ (GBK * B_LD)
#define GEMM_SMEM_BYTES (GSTAGES * (ASZ + BSZ) * 4)

template <bool GELU>
__global__ __launch_bounds__(256)
void gemm_kernel(const float* __restrict__ A, const float* __restrict__ W,
                 const float* __restrict__ bias, float* __restrict__ Out,
                 int M, int N, int Kd) {
    extern __shared__ float smem[];
    float* Asm = smem;                   // [GSTAGES][ASZ]
    float* Bsm = smem + GSTAGES * ASZ;   // [GSTAGES][BSZ]

    int e = blockIdx.z;
    int bm = blockIdx.y, bn = blockIdx.x;
    const float* Ae = A + (size_t)e * M * Kd;
    const float* We = W + (size_t)e * Kd * N;
    float* Oe = Out + (size_t)e * M * N;

    int tid = threadIdx.x;
    int warp = tid >> 5, lane = tid & 31;
    int g = lane >> 2, tig = lane & 3;
    int wm = warp >> 2;  // 0..1 (64 rows)
    int wn = warp & 3;   // 0..3 (32 cols)

    int a_row = tid >> 3;          // 0..31
    int a_col = (tid & 7) * 4;     // 0,4,...,28
    int b_row = tid >> 5;          // 0..7
    int b_col = (tid & 31) * 4;    // 0..124

    uint32_t sA = (uint32_t)__cvta_generic_to_shared(Asm);
    uint32_t sB = (uint32_t)__cvta_generic_to_shared(Bsm);

    const int nK = Kd / GBK;

    // issue one K-tile into a stage
    auto issue = [&](int kt, int st) {
        uint32_t aBase = sA + (uint32_t)(st * ASZ) * 4;
        uint32_t bBase = sB + (uint32_t)(st * BSZ) * 4;
#pragma unroll
        for (int p = 0; p < 4; p++) {
            int r = a_row + p * 32;
            const float* src = Ae + (size_t)(bm * GBM + r) * Kd + kt * GBK + a_col;
            cp_async16(aBase + (uint32_t)(r * A_LD + a_col) * 4, src);
        }
#pragma unroll
        for (int p = 0; p < 4; p++) {
            int r = b_row + p * 8;
            const float* src = We + (size_t)(kt * GBK + r) * N + bn * GBN + b_col;
            cp_async16(bBase + (uint32_t)(r * B_LD + b_col) * 4, src);
        }
        cp_commit();
    };

    // prefetch stages 0..GSTAGES-2
#pragma unroll
    for (int s = 0; s < GSTAGES - 1; s++) issue(s, s);

    float acc[4][4][4];
#pragma unroll
    for (int i = 0; i < 4; i++)
#pragma unroll
        for (int j = 0; j < 4; j++)
#pragma unroll
            for (int k = 0; k < 4; k++) acc[i][j][k] = 0.0f;

    for (int kt = 0; kt < nK; kt++) {
        if (kt < nK - 1) cp_wait<GSTAGES - 2>(); else cp_wait<0>();
        __syncthreads();

        // issue the tile GSTAGES-1 ahead (its buffer was consumed at kt-1)
        int nt = kt + GSTAGES - 1;
        if (nt < nK) issue(nt, nt % GSTAGES);

        const float* as = Asm + (kt % GSTAGES) * ASZ;
        const float* bs = Bsm + (kt % GSTAGES) * BSZ;

#pragma unroll
        for (int kk = 0; kk < 4; kk++) {
            int kb = kk * 8;
            uint32_t af[4][4];
#pragma unroll
            for (int mt = 0; mt < 4; mt++) {
                int r0 = wm * 64 + mt * 16 + g;
                af[mt][0] = __float_as_uint(as[r0 * A_LD + kb + tig]);
                af[mt][1] = __float_as_uint(as[(r0 + 8) * A_LD + kb + tig]);
                af[mt][2] = __float_as_uint(as[r0 * A_LD + kb + tig + 4]);
                af[mt][3] = __float_as_uint(as[(r0 + 8) * A_LD + kb + tig + 4]);
            }
            uint32_t bf[4][2];
#pragma unroll
            for (int nt2 = 0; nt2 < 4; nt2++) {
                int c0 = wn * 32 + nt2 * 8 + g;
                bf[nt2][0] = __float_as_uint(bs[(kb + tig) * B_LD + c0]);
                bf[nt2][1] = __float_as_uint(bs[(kb + tig + 4) * B_LD + c0]);
            }
#pragma unroll
            for (int mt = 0; mt < 4; mt++)
#pragma unroll
                for (int nt2 = 0; nt2 < 4; nt2++)
                    mma_tf32(acc[mt][nt2], af[mt], bf[nt2]);
        }
        __syncthreads();
    }

    // epilogue
#pragma unroll
    for (int mt = 0; mt < 4; mt++) {
        int r0 = bm * GBM + wm * 64 + mt * 16 + g;
#pragma unroll
        for (int nt2 = 0; nt2 < 4; nt2++) {
            int c0 = bn * GBN + wn * 32 + nt2 * 8 + 2 * tig;
            float bv0 = bias[(size_t)e * N + c0];
            float bv1 = bias[(size_t)e * N + c0 + 1];
            float v00 = acc[mt][nt2][0] + bv0;
            float v01 = acc[mt][nt2][1] + bv1;
            float v10 = acc[mt][nt2][2] + bv0;
            float v11 = acc[mt][nt2][3] + bv1;
            if (GELU) {
                // gelu then round to tf32 so GEMM2 consumes identical bits to
                // a load-time cvt (numerics unchanged vs round 1)
                v00 = to_tf32(gelu_tanh(v00)); v01 = to_tf32(gelu_tanh(v01));
                v10 = to_tf32(gelu_tanh(v10)); v11 = to_tf32(gelu_tanh(v11));
            }
            *(float2*)(Oe + (size_t)r0 * N + c0) = make_float2(v00, v01);
            *(float2*)(Oe + (size_t)(r0 + 8) * N + c0) = make_float2(v10, v11);
        }
    }
}

// ---------------- combine gather ---------------------------------------------
__global__ void combine_kernel(float* __restrict__ out) {
    int n = blockIdx.x;
    int l0 = g_loc[2 * n], l1 = g_loc[2 * n + 1];
    float w0 = (l0 >= 0) ? g_wf[2 * n] : 0.0f;
    float w1 = (l1 >= 0) ? g_wf[2 * n + 1] : 0.0f;
    const float4* y0 = (const float4*)(g_y + (size_t)max(l0, 0) * C_DIM);
    const float4* y1 = (const float4*)(g_y + (size_t)max(l1, 0) * C_DIM);
    float4* dst = (float4*)(out + (size_t)n * C_DIM);
    int t = threadIdx.x;  // 128
#pragma unroll
    for (int j = 0; j < 2; j++) {
        int idx = t + j * 128;
        float4 a = (l0 >= 0) ? y0[idx] : make_float4(0, 0, 0, 0);
        float4 b = (l1 >= 0) ? y1[idx] : make_float4(0, 0, 0, 0);
        float4 r;
        r.x = w0 * a.x + w1 * b.x;
        r.y = w0 * a.y + w1 * b.y;
        r.z = w0 * a.z + w1 * b.z;
        r.w = w0 * a.w + w1 * b.w;
        dst[idx] = r;
    }
}

// ---------------- launcher ----------------------------------------------------
extern "C" void kernel_launch(void* const* d_in, const int* in_sizes, int n_in,
                              void* d_out, int out_size) {
    const float* x      = (const float*)d_in[0];
    const float* w_gate = (const float*)d_in[1];
    const float* b_gate = (const float*)d_in[2];
    const float* W1     = (const float*)d_in[3];
    const float* b1     = (const float*)d_in[4];
    const float* W2     = (const float*)d_in[5];
    const float* b2     = (const float*)d_in[6];
    float* out = (float*)d_out;

    // allow >48KB dynamic smem for the GEMM (host-side attribute, not captured)
    cudaFuncSetAttribute(gemm_kernel<true>,
                         cudaFuncAttributeMaxDynamicSharedMemorySize, GEMM_SMEM_BYTES);
    cudaFuncSetAttribute(gemm_kernel<false>,
                         cudaFuncAttributeMaxDynamicSharedMemorySize, GEMM_SMEM_BYTES);

    float *disp = nullptr, *h = nullptr, *y = nullptr, *w1t = nullptr, *w2t = nullptr;
    cudaGetSymbolAddress((void**)&disp, g_disp);
    cudaGetSymbolAddress((void**)&h, g_h);
    cudaGetSymbolAddress((void**)&y, g_y);
    cudaGetSymbolAddress((void**)&w1t, g_W1t);
    cudaGetSymbolAddress((void**)&w2t, g_W2t);

    init_kernel<<<1, 32>>>();

    // round weights to tf32 once per launch (hoists all cvt out of mainloop)
    {
        int n4 = E_NUM * C_DIM * F_DIM / 4;
        round_kernel<<<(n4 + 255) / 256, 256>>>(W1, w1t, n4);
        round_kernel<<<(n4 + 255) / 256, 256>>>(W2, w2t, n4);
    }

    gate_kernel<<<N_TOK / 8, 256>>>(x, w_gate, b_gate);
    scan_kernel<<<1, 256>>>(out, out_size);
    dispatch_kernel<<<S_SLOTS, 128>>>(x);

    {
        dim3 grid1(F_DIM / GBN, CAP / GBM, E_NUM);
        gemm_kernel<true><<<grid1, 256, GEMM_SMEM_BYTES>>>(disp, w1t, b1, h, CAP, F_DIM, C_DIM);

        dim3 grid2(C_DIM / GBN, CAP / GBM, E_NUM);
        gemm_kernel<false><<<grid2, 256, GEMM_SMEM_BYTES>>>(h, w2t, b2, y, CAP, C_DIM, F_DIM);
    }

    combine_kernel<<<N_TOK, 128>>>(out);
}

// round 4
// speedup vs baseline: 1.1091x; 1.0093x over previous
#include <cuda_runtime.h>
#include <cstdint>

// Problem constants
#define N_TOK 8192
#define C_DIM 1024
#define F_DIM 4096
#define E_NUM 8
#define S_SLOTS (N_TOK * 2)
#define CAP 2048

// ---------------- scratch (static device globals; no allocation allowed) ----
__device__ float g_disp[(size_t)E_NUM * CAP * C_DIM];   // 64 MB (tf32-rounded)
__device__ float g_h[(size_t)E_NUM * CAP * F_DIM];      // 256 MB (tf32-rounded)
__device__ float g_y[(size_t)E_NUM * CAP * C_DIM];      // 64 MB
__device__ float g_W1t[(size_t)E_NUM * C_DIM * F_DIM];  // tf32-rounded W1
__device__ float g_W2t[(size_t)E_NUM * F_DIM * C_DIM];  // tf32-rounded W2
__device__ int   g_eidx[S_SLOTS];
__device__ float g_wf[S_SLOTS];
__device__ int   g_loc[S_SLOTS];
__device__ int   g_cnt[E_NUM];          // kept rows per expert (<= CAP)
__device__ float g_probs_sum[E_NUM];

// ---------------- helpers ----------------------------------------------------
__device__ __forceinline__ float gelu_tanh(float x) {
    const float k0 = 0.7978845608028654f;   // sqrt(2/pi)
    float x3 = x * x * x;
    float t = tanhf(k0 * (x + 0.044715f * x3));
    return 0.5f * x * (1.0f + t);
}

__device__ __forceinline__ float to_tf32(float x) {
    uint32_t u;
    asm("cvt.rna.tf32.f32 %0, %1;" : "=r"(u) : "f"(x));
    return __uint_as_float(u);
}

__device__ __forceinline__ void mma_tf32(float* d, const uint32_t* a, const uint32_t* b) {
    asm volatile(
        "mma.sync.aligned.m16n8k8.row.col.f32.tf32.tf32.f32 "
        "{%0,%1,%2,%3}, {%4,%5,%6,%7}, {%8,%9}, {%0,%1,%2,%3};"
        : "+f"(d[0]), "+f"(d[1]), "+f"(d[2]), "+f"(d[3])
        : "r"(a[0]), "r"(a[1]), "r"(a[2]), "r"(a[3]), "r"(b[0]), "r"(b[1]));
}

__device__ __forceinline__ void cp_async16(uint32_t smem_dst, const void* gmem_src) {
    asm volatile("cp.async.cg.shared.global [%0], [%1], 16;\n" :: "r"(smem_dst), "l"(gmem_src));
}
__device__ __forceinline__ void cp_commit() {
    asm volatile("cp.async.commit_group;\n");
}
template <int N>
__device__ __forceinline__ void cp_wait() {
    asm volatile("cp.async.wait_group %0;\n" :: "n"(N));
}

// ---------------- init -------------------------------------------------------
__global__ void init_kernel() {
    int t = threadIdx.x;
    if (t < E_NUM) g_probs_sum[t] = 0.0f;
}

// ---------------- weight rounding (tf32, once per launch) ---------------------
__global__ void round_kernel(const float* __restrict__ src, float* __restrict__ dst, int n4) {
    int i = blockIdx.x * blockDim.x + threadIdx.x;
    if (i >= n4) return;
    float4 v = ((const float4*)src)[i];
    v.x = to_tf32(v.x); v.y = to_tf32(v.y);
    v.z = to_tf32(v.z); v.w = to_tf32(v.w);
    ((float4*)dst)[i] = v;
}

// ---------------- gating: logits -> softmax -> top2 --------------------------
__global__ void gate_kernel(const float* __restrict__ x,
                            const float* __restrict__ w_gate,
                            const float* __restrict__ b_gate) {
    __shared__ float sprob[E_NUM];
    int tid = threadIdx.x;
    if (tid < E_NUM) sprob[tid] = 0.0f;
    __syncthreads();

    int warp = tid >> 5, lane = tid & 31;
    int n = blockIdx.x * 8 + warp;
    const float* xr = x + (size_t)n * C_DIM;

    float acc[E_NUM];
#pragma unroll
    for (int e = 0; e < E_NUM; e++) acc[e] = 0.0f;

    for (int c = lane; c < C_DIM; c += 32) {
        float xv = xr[c];
        const float4* w4 = (const float4*)(w_gate + (size_t)c * E_NUM);
        float4 wa = w4[0], wb = w4[1];
        acc[0] += xv * wa.x; acc[1] += xv * wa.y;
        acc[2] += xv * wa.z; acc[3] += xv * wa.w;
        acc[4] += xv * wb.x; acc[5] += xv * wb.y;
        acc[6] += xv * wb.z; acc[7] += xv * wb.w;
    }
#pragma unroll
    for (int e = 0; e < E_NUM; e++)
#pragma unroll
        for (int o = 16; o > 0; o >>= 1)
            acc[e] += __shfl_down_sync(0xffffffffu, acc[e], o);

    if (lane == 0) {
        float p[E_NUM];
        float mx = -1e30f;
#pragma unroll
        for (int e = 0; e < E_NUM; e++) {
            p[e] = acc[e] + b_gate[e];
            mx = fmaxf(mx, p[e]);
        }
        float s = 0.0f;
#pragma unroll
        for (int e = 0; e < E_NUM; e++) { p[e] = expf(p[e] - mx); s += p[e]; }
        float inv = 1.0f / s;
#pragma unroll
        for (int e = 0; e < E_NUM; e++) p[e] *= inv;

        int i0 = 0;
#pragma unroll
        for (int e = 1; e < E_NUM; e++) if (p[e] > p[i0]) i0 = e;
        int i1 = (i0 == 0) ? 1 : 0;
#pragma unroll
        for (int e = 0; e < E_NUM; e++) if (e != i0 && p[e] > p[i1]) i1 = e;

        float w0 = p[i0], w1 = p[i1];
        float ws = w0 + w1 + 1e-9f;
        g_eidx[2 * n]     = i0;
        g_eidx[2 * n + 1] = i1;
        g_wf[2 * n]       = w0 / ws;
        g_wf[2 * n + 1]   = w1 / ws;
#pragma unroll
        for (int e = 0; e < E_NUM; e++) atomicAdd(&sprob[e], p[e]);
    }
    __syncthreads();
    if (tid < E_NUM) atomicAdd(&g_probs_sum[tid], sprob[tid]);
}

// ---------------- FCFS capacity scan + aux loss -------------------------------
__global__ void scan_kernel(float* __restrict__ d_out, int out_size) {
    const int PER = 64;
    int t = threadIdx.x;
    int base = t * PER;

    int cnt[E_NUM];
#pragma unroll
    for (int e = 0; e < E_NUM; e++) cnt[e] = 0;
    for (int i = 0; i < PER; i++) cnt[g_eidx[base + i]]++;

    unsigned long long lo = 0, hi = 0;
#pragma unroll
    for (int e = 0; e < 4; e++) {
        lo |= (unsigned long long)cnt[e] << (16 * e);
        hi |= (unsigned long long)cnt[e + 4] << (16 * e);
    }

    __shared__ unsigned long long s0[256], s1[256];
    s0[t] = lo; s1[t] = hi;
    __syncthreads();
    for (int off = 1; off < 256; off <<= 1) {
        unsigned long long v0 = 0, v1 = 0;
        if (t >= off) { v0 = s0[t - off]; v1 = s1[t - off]; }
        __syncthreads();
        s0[t] += v0; s1[t] += v1;
        __syncthreads();
    }
    unsigned long long p0 = (t > 0) ? s0[t - 1] : 0ULL;
    unsigned long long p1 = (t > 0) ? s1[t - 1] : 0ULL;

    int exc[E_NUM];
#pragma unroll
    for (int e = 0; e < 4; e++) {
        exc[e]     = (int)((p0 >> (16 * e)) & 0xffffULL);
        exc[e + 4] = (int)((p1 >> (16 * e)) & 0xffffULL);
    }
    for (int i = 0; i < PER; i++) {
        int s = base + i;
        int e = g_eidx[s];
        int pos = exc[e]++;
        g_loc[s] = (pos < CAP) ? (e * CAP + pos) : -1;
    }

    if (t == 0) {
        unsigned long long t0 = s0[255], t1 = s1[255];
        float sumload = 0.0f, load[E_NUM];
#pragma unroll
        for (int e = 0; e < 4; e++) {
            int c0 = (int)((t0 >> (16 * e)) & 0xffffULL);
            int c1 = (int)((t1 >> (16 * e)) & 0xffffULL);
            g_cnt[e]     = min(c0, CAP);
            g_cnt[e + 4] = min(c1, CAP);
            load[e]     = (float)min(c0, CAP);
            load[e + 4] = (float)min(c1, CAP);
        }
#pragma unroll
        for (int e = 0; e < E_NUM; e++) sumload += load[e];
        float fe[E_NUM], sfe = 0.0f;
#pragma unroll
        for (int e = 0; e < E_NUM; e++) { fe[e] = g_probs_sum[e] / (float)N_TOK; sfe += fe[e]; }
        float aux = 0.0f;
#pragma unroll
        for (int e = 0; e < E_NUM; e++) {
            float fn = fe[e] / (sfe + 1e-9f);
            float fa = load[e] / (sumload + 1e-9f);
            float d = fn - fa;
            aux += d * d;
        }
        aux = 0.01f * aux / (float)E_NUM;
        if (out_size > N_TOK * C_DIM)
            d_out[(size_t)N_TOK * C_DIM] = aux;
    }
}

// ---------------- dispatch gather (tf32-rounded at write) ---------------------
__global__ void dispatch_kernel(const float* __restrict__ x) {
    int s = blockIdx.x;
    int loc = g_loc[s];
    if (loc < 0) return;
    const float4* src = (const float4*)(x + ((size_t)(s >> 1)) * C_DIM);
    float4* dst = (float4*)(g_disp + (size_t)loc * C_DIM);
    int t = threadIdx.x;  // 128
#pragma unroll
    for (int j = 0; j < 2; j++) {
        float4 v = src[t + j * 128];
        v.x = to_tf32(v.x); v.y = to_tf32(v.y);
        v.z = to_tf32(v.z); v.w = to_tf32(v.w);
        dst[t + j * 128] = v;
    }
}

// ---------------- grouped GEMM: TF32 mma.sync, 3-stage cp.async pipeline -----
// A: [E*M][K] row-major (tf32-rounded), W: [E][K][N] row-major (rounded),
// bias [E][N], Out [E*M][N]. Tiles: 128x128x32, 256 threads, 8 warps,
// 2 CTAs/SM for TLP.
#define GBM 128
#define GBN 128
#define GBK 32
#define GSTAGES 3
#define A_LD 36
#define B_LD 132
#define ASZ (GBM * A_LD)
#define BSZ (GBK * B_LD)
#define GEMM_SMEM_BYTES (GSTAGES * (ASZ + BSZ) * 4)

template <bool GELU>
__global__ __launch_bounds__(256, 2)
void gemm_kernel(const float* __restrict__ A, const float* __restrict__ W,
                 const float* __restrict__ bias, float* __restrict__ Out,
                 int M, int N, int Kd) {
    int e = blockIdx.z;
    int bm = blockIdx.y, bn = blockIdx.x;

    // early-exit: rows >= kept-count for this expert are never read downstream
    if (bm * GBM >= g_cnt[e]) return;

    extern __shared__ float smem[];
    float* Asm = smem;                   // [GSTAGES][ASZ]
    float* Bsm = smem + GSTAGES * ASZ;   // [GSTAGES][BSZ]

    const float* Ae = A + (size_t)e * M * Kd;
    const float* We = W + (size_t)e * Kd * N;
    float* Oe = Out + (size_t)e * M * N;

    int tid = threadIdx.x;
    int warp = tid >> 5, lane = tid & 31;
    int g = lane >> 2, tig = lane & 3;
    int wm = warp >> 2;  // 0..1 (64 rows)
    int wn = warp & 3;   // 0..3 (32 cols)

    int a_row = tid >> 3;          // 0..31
    int a_col = (tid & 7) * 4;     // 0,4,...,28
    int b_row = tid >> 5;          // 0..7
    int b_col = (tid & 31) * 4;    // 0..124

    uint32_t sA = (uint32_t)__cvta_generic_to_shared(Asm);
    uint32_t sB = (uint32_t)__cvta_generic_to_shared(Bsm);

    const int nK = Kd / GBK;

    auto issue = [&](int kt, int st) {
        uint32_t aBase = sA + (uint32_t)(st * ASZ) * 4;
        uint32_t bBase = sB + (uint32_t)(st * BSZ) * 4;
#pragma unroll
        for (int p = 0; p < 4; p++) {
            int r = a_row + p * 32;
            const float* src = Ae + (size_t)(bm * GBM + r) * Kd + kt * GBK + a_col;
            cp_async16(aBase + (uint32_t)(r * A_LD + a_col) * 4, src);
        }
#pragma unroll
        for (int p = 0; p < 4; p++) {
            int r = b_row + p * 8;
            const float* src = We + (size_t)(kt * GBK + r) * N + bn * GBN + b_col;
            cp_async16(bBase + (uint32_t)(r * B_LD + b_col) * 4, src);
        }
        cp_commit();
    };

#pragma unroll
    for (int s = 0; s < GSTAGES - 1; s++) issue(s, s);

    float acc[4][4][4];
#pragma unroll
    for (int i = 0; i < 4; i++)
#pragma unroll
        for (int j = 0; j < 4; j++)
#pragma unroll
            for (int k = 0; k < 4; k++) acc[i][j][k] = 0.0f;

    for (int kt = 0; kt < nK; kt++) {
        if (kt < nK - 1) cp_wait<GSTAGES - 2>(); else cp_wait<0>();
        __syncthreads();

        int nt = kt + GSTAGES - 1;
        if (nt < nK) issue(nt, nt % GSTAGES);

        const float* as = Asm + (kt % GSTAGES) * ASZ;
        const float* bs = Bsm + (kt % GSTAGES) * BSZ;

#pragma unroll
        for (int kk = 0; kk < 4; kk++) {
            int kb = kk * 8;
            uint32_t af[4][4];
#pragma unroll
            for (int mt = 0; mt < 4; mt++) {
                int r0 = wm * 64 + mt * 16 + g;
                af[mt][0] = __float_as_uint(as[r0 * A_LD + kb + tig]);
                af[mt][1] = __float_as_uint(as[(r0 + 8) * A_LD + kb + tig]);
                af[mt][2] = __float_as_uint(as[r0 * A_LD + kb + tig + 4]);
                af[mt][3] = __float_as_uint(as[(r0 + 8) * A_LD + kb + tig + 4]);
            }
            uint32_t bf[4][2];
#pragma unroll
            for (int nt2 = 0; nt2 < 4; nt2++) {
                int c0 = wn * 32 + nt2 * 8 + g;
                bf[nt2][0] = __float_as_uint(bs[(kb + tig) * B_LD + c0]);
                bf[nt2][1] = __float_as_uint(bs[(kb + tig + 4) * B_LD + c0]);
            }
#pragma unroll
            for (int mt = 0; mt < 4; mt++)
#pragma unroll
                for (int nt2 = 0; nt2 < 4; nt2++)
                    mma_tf32(acc[mt][nt2], af[mt], bf[nt2]);
        }
        __syncthreads();
    }

    // epilogue
#pragma unroll
    for (int mt = 0; mt < 4; mt++) {
        int r0 = bm * GBM + wm * 64 + mt * 16 + g;
#pragma unroll
        for (int nt2 = 0; nt2 < 4; nt2++) {
            int c0 = bn * GBN + wn * 32 + nt2 * 8 + 2 * tig;
            float bv0 = bias[(size_t)e * N + c0];
            float bv1 = bias[(size_t)e * N + c0 + 1];
            float v00 = acc[mt][nt2][0] + bv0;
            float v01 = acc[mt][nt2][1] + bv1;
            float v10 = acc[mt][nt2][2] + bv0;
            float v11 = acc[mt][nt2][3] + bv1;
            if (GELU) {
                v00 = to_tf32(gelu_tanh(v00)); v01 = to_tf32(gelu_tanh(v01));
                v10 = to_tf32(gelu_tanh(v10)); v11 = to_tf32(gelu_tanh(v11));
            }
            *(float2*)(Oe + (size_t)r0 * N + c0) = make_float2(v00, v01);
            *(float2*)(Oe + (size_t)(r0 + 8) * N + c0) = make_float2(v10, v11);
        }
    }
}

// ---------------- combine gather ---------------------------------------------
__global__ void combine_kernel(float* __restrict__ out) {
    int n = blockIdx.x;
    int l0 = g_loc[2 * n], l1 = g_loc[2 * n + 1];
    float w0 = (l0 >= 0) ? g_wf[2 * n] : 0.0f;
    float w1 = (l1 >= 0) ? g_wf[2 * n + 1] : 0.0f;
    const float4* y0 = (const float4*)(g_y + (size_t)max(l0, 0) * C_DIM);
    const float4* y1 = (const float4*)(g_y + (size_t)max(l1, 0) * C_DIM);
    float4* dst = (float4*)(out + (size_t)n * C_DIM);
    int t = threadIdx.x;  // 128
#pragma unroll
    for (int j = 0; j < 2; j++) {
        int idx = t + j * 128;
        float4 a = (l0 >= 0) ? y0[idx] : make_float4(0, 0, 0, 0);
        float4 b = (l1 >= 0) ? y1[idx] : make_float4(0, 0, 0, 0);
        float4 r;
        r.x = w0 * a.x + w1 * b.x;
        r.y = w0 * a.y + w1 * b.y;
        r.z = w0 * a.z + w1 * b.z;
        r.w = w0 * a.w + w1 * b.w;
        dst[idx] = r;
    }
}

// ---------------- launcher ----------------------------------------------------
extern "C" void kernel_launch(void* const* d_in, const int* in_sizes, int n_in,
                              void* d_out, int out_size) {
    const float* x      = (const float*)d_in[0];
    const float* w_gate = (const float*)d_in[1];
    const float* b_gate = (const float*)d_in[2];
    const float* W1     = (const float*)d_in[3];
    const float* b1     = (const float*)d_in[4];
    const float* W2     = (const float*)d_in[5];
    const float* b2     = (const float*)d_in[6];
    float* out = (float*)d_out;

    cudaFuncSetAttribute(gemm_kernel<true>,
                         cudaFuncAttributeMaxDynamicSharedMemorySize, GEMM_SMEM_BYTES);
    cudaFuncSetAttribute(gemm_kernel<false>,
                         cudaFuncAttributeMaxDynamicSharedMemorySize, GEMM_SMEM_BYTES);

    float *disp = nullptr, *h = nullptr, *y = nullptr, *w1t = nullptr, *w2t = nullptr;
    cudaGetSymbolAddress((void**)&disp, g_disp);
    cudaGetSymbolAddress((void**)&h, g_h);
    cudaGetSymbolAddress((void**)&y, g_y);
    cudaGetSymbolAddress((void**)&w1t, g_W1t);
    cudaGetSymbolAddress((void**)&w2t, g_W2t);

    init_kernel<<<1, 32>>>();

    {
        int n4 = E_NUM * C_DIM * F_DIM / 4;
        round_kernel<<<(n4 + 255) / 256, 256>>>(W1, w1t, n4);
        round_kernel<<<(n4 + 255) / 256, 256>>>(W2, w2t, n4);
    }

    gate_kernel<<<N_TOK / 8, 256>>>(x, w_gate, b_gate);
    scan_kernel<<<1, 256>>>(out, out_size);
    dispatch_kernel<<<S_SLOTS, 128>>>(x);

    {
        dim3 grid1(F_DIM / GBN, CAP / GBM, E_NUM);
        gemm_kernel<true><<<grid1, 256, GEMM_SMEM_BYTES>>>(disp, w1t, b1, h, CAP, F_DIM, C_DIM);

        dim3 grid2(C_DIM / GBN, CAP / GBM, E_NUM);
        gemm_kernel<false><<<grid2, 256, GEMM_SMEM_BYTES>>>(h, w2t, b2, y, CAP, C_DIM, F_DIM);
    }

    combine_kernel<<<N_TOK, 128>>>(out);
}

// round 5
// speedup vs baseline: 1.8201x; 1.6410x over previous
#include <cuda_runtime.h>
#include <cuda_fp16.h>
#include <cstdint>

// Problem constants
#define N_TOK 8192
#define C_DIM 1024
#define F_DIM 4096
#define E_NUM 8
#define S_SLOTS (N_TOK * 2)
#define CAP 2048

// ---------------- scratch (static device globals) ----------------------------
__device__ __half g_disp[(size_t)E_NUM * CAP * C_DIM];   // 32 MB fp16
__device__ __half g_h[(size_t)E_NUM * CAP * F_DIM];      // 128 MB fp16
__device__ float  g_y[(size_t)E_NUM * CAP * C_DIM];      // 64 MB
__device__ __half g_W1h[(size_t)E_NUM * F_DIM * C_DIM];  // W1^T per expert [F][C] fp16
__device__ __half g_W2h[(size_t)E_NUM * C_DIM * F_DIM];  // W2^T per expert [C][F] fp16
__device__ int    g_eidx[S_SLOTS];
__device__ float  g_wf[S_SLOTS];
__device__ int    g_loc[S_SLOTS];
__device__ int    g_cnt[E_NUM];
__device__ float  g_probs_sum[E_NUM];

// ---------------- helpers ----------------------------------------------------
__device__ __forceinline__ float gelu_tanh(float x) {
    const float k0 = 0.7978845608028654f;
    float x3 = x * x * x;
    float t = tanhf(k0 * (x + 0.044715f * x3));
    return 0.5f * x * (1.0f + t);
}

// fp16 m16n8k16, fp32 accumulate
__device__ __forceinline__ void mma_f16(float* d, const uint32_t* a, const uint32_t* b) {
    asm volatile(
        "mma.sync.aligned.m16n8k16.row.col.f32.f16.f16.f32 "
        "{%0,%1,%2,%3}, {%4,%5,%6,%7}, {%8,%9}, {%0,%1,%2,%3};"
        : "+f"(d[0]), "+f"(d[1]), "+f"(d[2]), "+f"(d[3])
        : "r"(a[0]), "r"(a[1]), "r"(a[2]), "r"(a[3]), "r"(b[0]), "r"(b[1]));
}

__device__ __forceinline__ void cp_async16(uint32_t smem_dst, const void* gmem_src) {
    asm volatile("cp.async.cg.shared.global [%0], [%1], 16;\n" :: "r"(smem_dst), "l"(gmem_src));
}
__device__ __forceinline__ void cp_commit() {
    asm volatile("cp.async.commit_group;\n");
}
template <int N>
__device__ __forceinline__ void cp_wait() {
    asm volatile("cp.async.wait_group %0;\n" :: "n"(N));
}

// ---------------- init -------------------------------------------------------
__global__ void init_kernel() {
    int t = threadIdx.x;
    if (t < E_NUM) g_probs_sum[t] = 0.0f;
}

// ---------------- weight transpose + fp16 convert: [E][K][N] -> [E][N][K] -----
__global__ void transpose_h_kernel(const float* __restrict__ src,
                                   __half* __restrict__ dst, int K, int N) {
    __shared__ float t[32][33];
    int e = blockIdx.z;
    const float* s = src + (size_t)e * K * N;
    __half* d = dst + (size_t)e * N * K;
    int x = blockIdx.x * 32 + threadIdx.x;   // N index
    int y0 = blockIdx.y * 32;                // K base
#pragma unroll
    for (int j = 0; j < 32; j += 8)
        t[threadIdx.y + j][threadIdx.x] = s[(size_t)(y0 + threadIdx.y + j) * N + x];
    __syncthreads();
    int xo = y0 + threadIdx.x;               // K index
    int yo = blockIdx.x * 32;                // N base
#pragma unroll
    for (int j = 0; j < 32; j += 8)
        d[(size_t)(yo + threadIdx.y + j) * K + xo] = __float2half_rn(t[threadIdx.x][threadIdx.y + j]);
}

// ---------------- gating -------------------------------------------------------
__global__ void gate_kernel(const float* __restrict__ x,
                            const float* __restrict__ w_gate,
                            const float* __restrict__ b_gate) {
    __shared__ float sprob[E_NUM];
    int tid = threadIdx.x;
    if (tid < E_NUM) sprob[tid] = 0.0f;
    __syncthreads();

    int warp = tid >> 5, lane = tid & 31;
    int n = blockIdx.x * 8 + warp;
    const float* xr = x + (size_t)n * C_DIM;

    float acc[E_NUM];
#pragma unroll
    for (int e = 0; e < E_NUM; e++) acc[e] = 0.0f;

    for (int c = lane; c < C_DIM; c += 32) {
        float xv = xr[c];
        const float4* w4 = (const float4*)(w_gate + (size_t)c * E_NUM);
        float4 wa = w4[0], wb = w4[1];
        acc[0] += xv * wa.x; acc[1] += xv * wa.y;
        acc[2] += xv * wa.z; acc[3] += xv * wa.w;
        acc[4] += xv * wb.x; acc[5] += xv * wb.y;
        acc[6] += xv * wb.z; acc[7] += xv * wb.w;
    }
#pragma unroll
    for (int e = 0; e < E_NUM; e++)
#pragma unroll
        for (int o = 16; o > 0; o >>= 1)
            acc[e] += __shfl_down_sync(0xffffffffu, acc[e], o);

    if (lane == 0) {
        float p[E_NUM];
        float mx = -1e30f;
#pragma unroll
        for (int e = 0; e < E_NUM; e++) { p[e] = acc[e] + b_gate[e]; mx = fmaxf(mx, p[e]); }
        float s = 0.0f;
#pragma unroll
        for (int e = 0; e < E_NUM; e++) { p[e] = expf(p[e] - mx); s += p[e]; }
        float inv = 1.0f / s;
#pragma unroll
        for (int e = 0; e < E_NUM; e++) p[e] *= inv;

        int i0 = 0;
#pragma unroll
        for (int e = 1; e < E_NUM; e++) if (p[e] > p[i0]) i0 = e;
        int i1 = (i0 == 0) ? 1 : 0;
#pragma unroll
        for (int e = 0; e < E_NUM; e++) if (e != i0 && p[e] > p[i1]) i1 = e;

        float w0 = p[i0], w1 = p[i1];
        float ws = w0 + w1 + 1e-9f;
        g_eidx[2 * n]     = i0;
        g_eidx[2 * n + 1] = i1;
        g_wf[2 * n]       = w0 / ws;
        g_wf[2 * n + 1]   = w1 / ws;
#pragma unroll
        for (int e = 0; e < E_NUM; e++) atomicAdd(&sprob[e], p[e]);
    }
    __syncthreads();
    if (tid < E_NUM) atomicAdd(&g_probs_sum[tid], sprob[tid]);
}

// ---------------- FCFS capacity scan + aux loss --------------------------------
__global__ void scan_kernel(float* __restrict__ d_out, int out_size) {
    const int PER = 64;
    int t = threadIdx.x;
    int base = t * PER;

    int cnt[E_NUM];
#pragma unroll
    for (int e = 0; e < E_NUM; e++) cnt[e] = 0;
    for (int i = 0; i < PER; i++) cnt[g_eidx[base + i]]++;

    unsigned long long lo = 0, hi = 0;
#pragma unroll
    for (int e = 0; e < 4; e++) {
        lo |= (unsigned long long)cnt[e] << (16 * e);
        hi |= (unsigned long long)cnt[e + 4] << (16 * e);
    }

    __shared__ unsigned long long s0[256], s1[256];
    s0[t] = lo; s1[t] = hi;
    __syncthreads();
    for (int off = 1; off < 256; off <<= 1) {
        unsigned long long v0 = 0, v1 = 0;
        if (t >= off) { v0 = s0[t - off]; v1 = s1[t - off]; }
        __syncthreads();
        s0[t] += v0; s1[t] += v1;
        __syncthreads();
    }
    unsigned long long p0 = (t > 0) ? s0[t - 1] : 0ULL;
    unsigned long long p1 = (t > 0) ? s1[t - 1] : 0ULL;

    int exc[E_NUM];
#pragma unroll
    for (int e = 0; e < 4; e++) {
        exc[e]     = (int)((p0 >> (16 * e)) & 0xffffULL);
        exc[e + 4] = (int)((p1 >> (16 * e)) & 0xffffULL);
    }
    for (int i = 0; i < PER; i++) {
        int s = base + i;
        int e = g_eidx[s];
        int pos = exc[e]++;
        g_loc[s] = (pos < CAP) ? (e * CAP + pos) : -1;
    }

    if (t == 0) {
        unsigned long long t0 = s0[255], t1 = s1[255];
        float sumload = 0.0f, load[E_NUM];
#pragma unroll
        for (int e = 0; e < 4; e++) {
            int c0 = (int)((t0 >> (16 * e)) & 0xffffULL);
            int c1 = (int)((t1 >> (16 * e)) & 0xffffULL);
            g_cnt[e]     = min(c0, CAP);
            g_cnt[e + 4] = min(c1, CAP);
            load[e]     = (float)min(c0, CAP);
            load[e + 4] = (float)min(c1, CAP);
        }
#pragma unroll
        for (int e = 0; e < E_NUM; e++) sumload += load[e];
        float fe[E_NUM], sfe = 0.0f;
#pragma unroll
        for (int e = 0; e < E_NUM; e++) { fe[e] = g_probs_sum[e] / (float)N_TOK; sfe += fe[e]; }
        float aux = 0.0f;
#pragma unroll
        for (int e = 0; e < E_NUM; e++) {
            float fn = fe[e] / (sfe + 1e-9f);
            float fa = load[e] / (sumload + 1e-9f);
            float d = fn - fa;
            aux += d * d;
        }
        aux = 0.01f * aux / (float)E_NUM;
        if (out_size > N_TOK * C_DIM)
            d_out[(size_t)N_TOK * C_DIM] = aux;
    }
}

// ---------------- dispatch gather (fp16 convert at write) ----------------------
__global__ void dispatch_kernel(const float* __restrict__ x) {
    int s = blockIdx.x;
    int loc = g_loc[s];
    if (loc < 0) return;
    const float4* src = (const float4*)(x + ((size_t)(s >> 1)) * C_DIM);
    __half* dst = g_disp + (size_t)loc * C_DIM;
    int t = threadIdx.x;  // 128: each thread converts 8 floats -> one 16B store
    float4 v0 = src[2 * t];
    float4 v1 = src[2 * t + 1];
    __half2 h[4];
    h[0] = __floats2half2_rn(v0.x, v0.y);
    h[1] = __floats2half2_rn(v0.z, v0.w);
    h[2] = __floats2half2_rn(v1.x, v1.y);
    h[3] = __floats2half2_rn(v1.z, v1.w);
    *(uint4*)(dst + 8 * t) = *(uint4*)h;
}

// ---------------- grouped GEMM: fp16 mma.sync m16n8k16, 4-stage cp.async ------
// A: [E*M][K] half row-major, Bt: [E][N][K] half (pre-transposed),
// bias [E][N] float, Out [E*M][N] (half if GELU path, float otherwise).
#define GBM 128
#define GBN 128
#define GBK 32
#define GST 4
#define LDH 40                       // halfs per smem row (pad 8)
#define ASZH (GBM * LDH)             // 5120 halfs
#define BSZH (GBN * LDH)
#define STG_BYTES ((ASZH + BSZH) * 2)          // 20480
#define GEMM_SMEM_BYTES (GST * STG_BYTES)      // 81920

template <bool GELU, typename OT>
__global__ __launch_bounds__(256, 2)
void gemm_kernel(const __half* __restrict__ A, const __half* __restrict__ Bt,
                 const float* __restrict__ bias, OT* __restrict__ Out,
                 int M, int N, int Kd) {
    int e = blockIdx.z;
    int bm = blockIdx.y, bn = blockIdx.x;
    if (bm * GBM >= g_cnt[e]) return;   // rows never read downstream

    extern __shared__ __half smem[];
    __half* Asm = smem;                        // [GST][ASZH]
    __half* Bsm = smem + GST * ASZH;           // [GST][BSZH]

    const __half* Ae = A + (size_t)e * M * Kd;
    const __half* Be = Bt + (size_t)e * N * Kd;
    OT* Oe = Out + (size_t)e * M * N;

    int tid = threadIdx.x;
    int warp = tid >> 5, lane = tid & 31;
    int g = lane >> 2, tig = lane & 3;
    int wm = warp >> 2;  // 0..1 (64 rows)
    int wn = warp & 3;   // 0..3 (32 cols)

    uint32_t sA = (uint32_t)__cvta_generic_to_shared(Asm);
    uint32_t sB = (uint32_t)__cvta_generic_to_shared(Bsm);

    const int nK = Kd / GBK;

    // one K-tile (A: 128x32 halfs, B: 128x32 halfs) => 512 16B chunks each
    auto issue = [&](int kt, int st) {
        uint32_t aBase = sA + (uint32_t)(st * ASZH) * 2;
        uint32_t bBase = sB + (uint32_t)(st * BSZH) * 2;
#pragma unroll
        for (int i = 0; i < 2; i++) {
            int ch = tid + 256 * i;
            int r = ch >> 2, c = (ch & 3) * 8;
            cp_async16(aBase + (uint32_t)(r * LDH + c) * 2,
                       Ae + (size_t)(bm * GBM + r) * Kd + kt * GBK + c);
        }
#pragma unroll
        for (int i = 0; i < 2; i++) {
            int ch = tid + 256 * i;
            int r = ch >> 2, c = (ch & 3) * 8;
            cp_async16(bBase + (uint32_t)(r * LDH + c) * 2,
                       Be + (size_t)(bn * GBN + r) * Kd + kt * GBK + c);
        }
        cp_commit();
    };

#pragma unroll
    for (int s = 0; s < GST - 1; s++) issue(s, s);

    float acc[4][4][4];
#pragma unroll
    for (int i = 0; i < 4; i++)
#pragma unroll
        for (int j = 0; j < 4; j++)
#pragma unroll
            for (int k = 0; k < 4; k++) acc[i][j][k] = 0.0f;

    for (int kt = 0; kt < nK; kt++) {
        int rem = nK - 1 - kt;
        if (rem >= GST - 2) cp_wait<GST - 2>();
        else if (rem == 1)  cp_wait<1>();
        else                cp_wait<0>();
        __syncthreads();

        int nt = kt + GST - 1;
        if (nt < nK) issue(nt, nt % GST);

        const __half* as = Asm + (kt % GST) * ASZH;
        const __half* bs = Bsm + (kt % GST) * BSZH;

#pragma unroll
        for (int kk = 0; kk < 2; kk++) {
            int kb = kk * 16;
            uint32_t af[4][4];
#pragma unroll
            for (int mt = 0; mt < 4; mt++) {
                int r0 = wm * 64 + mt * 16 + g;
                af[mt][0] = *(const uint32_t*)&as[r0 * LDH + kb + 2 * tig];
                af[mt][1] = *(const uint32_t*)&as[(r0 + 8) * LDH + kb + 2 * tig];
                af[mt][2] = *(const uint32_t*)&as[r0 * LDH + kb + 8 + 2 * tig];
                af[mt][3] = *(const uint32_t*)&as[(r0 + 8) * LDH + kb + 8 + 2 * tig];
            }
            uint32_t bf[4][2];
#pragma unroll
            for (int nt2 = 0; nt2 < 4; nt2++) {
                int c0 = wn * 32 + nt2 * 8 + g;
                bf[nt2][0] = *(const uint32_t*)&bs[c0 * LDH + kb + 2 * tig];
                bf[nt2][1] = *(const uint32_t*)&bs[c0 * LDH + kb + 8 + 2 * tig];
            }
#pragma unroll
            for (int mt = 0; mt < 4; mt++)
#pragma unroll
                for (int nt2 = 0; nt2 < 4; nt2++)
                    mma_f16(acc[mt][nt2], af[mt], bf[nt2]);
        }
        __syncthreads();
    }

    // epilogue
#pragma unroll
    for (int mt = 0; mt < 4; mt++) {
        int r0 = bm * GBM + wm * 64 + mt * 16 + g;
#pragma unroll
        for (int nt2 = 0; nt2 < 4; nt2++) {
            int c0 = bn * GBN + wn * 32 + nt2 * 8 + 2 * tig;
            float bv0 = bias[(size_t)e * N + c0];
            float bv1 = bias[(size_t)e * N + c0 + 1];
            float v00 = acc[mt][nt2][0] + bv0;
            float v01 = acc[mt][nt2][1] + bv1;
            float v10 = acc[mt][nt2][2] + bv0;
            float v11 = acc[mt][nt2][3] + bv1;
            if (GELU) {
                v00 = gelu_tanh(v00); v01 = gelu_tanh(v01);
                v10 = gelu_tanh(v10); v11 = gelu_tanh(v11);
            }
            if constexpr (sizeof(OT) == 2) {
                *(__half2*)((__half*)Oe + (size_t)r0 * N + c0) = __floats2half2_rn(v00, v01);
                *(__half2*)((__half*)Oe + (size_t)(r0 + 8) * N + c0) = __floats2half2_rn(v10, v11);
            } else {
                *(float2*)((float*)Oe + (size_t)r0 * N + c0) = make_float2(v00, v01);
                *(float2*)((float*)Oe + (size_t)(r0 + 8) * N + c0) = make_float2(v10, v11);
            }
        }
    }
}

// ---------------- combine gather ---------------------------------------------
__global__ void combine_kernel(float* __restrict__ out) {
    int n = blockIdx.x;
    int l0 = g_loc[2 * n], l1 = g_loc[2 * n + 1];
    float w0 = (l0 >= 0) ? g_wf[2 * n] : 0.0f;
    float w1 = (l1 >= 0) ? g_wf[2 * n + 1] : 0.0f;
    const float4* y0 = (const float4*)(g_y + (size_t)max(l0, 0) * C_DIM);
    const float4* y1 = (const float4*)(g_y + (size_t)max(l1, 0) * C_DIM);
    float4* dst = (float4*)(out + (size_t)n * C_DIM);
    int t = threadIdx.x;  // 128
#pragma unroll
    for (int j = 0; j < 2; j++) {
        int idx = t + j * 128;
        float4 a = (l0 >= 0) ? y0[idx] : make_float4(0, 0, 0, 0);
        float4 b = (l1 >= 0) ? y1[idx] : make_float4(0, 0, 0, 0);
        float4 r;
        r.x = w0 * a.x + w1 * b.x;
        r.y = w0 * a.y + w1 * b.y;
        r.z = w0 * a.z + w1 * b.z;
        r.w = w0 * a.w + w1 * b.w;
        dst[idx] = r;
    }
}

// ---------------- launcher ----------------------------------------------------
extern "C" void kernel_launch(void* const* d_in, const int* in_sizes, int n_in,
                              void* d_out, int out_size) {
    const float* x      = (const float*)d_in[0];
    const float* w_gate = (const float*)d_in[1];
    const float* b_gate = (const float*)d_in[2];
    const float* W1     = (const float*)d_in[3];
    const float* b1     = (const float*)d_in[4];
    const float* W2     = (const float*)d_in[5];
    const float* b2     = (const float*)d_in[6];
    float* out = (float*)d_out;

    cudaFuncSetAttribute((const void*)gemm_kernel<true, __half>,
                         cudaFuncAttributeMaxDynamicSharedMemorySize, GEMM_SMEM_BYTES);
    cudaFuncSetAttribute((const void*)gemm_kernel<false, float>,
                         cudaFuncAttributeMaxDynamicSharedMemorySize, GEMM_SMEM_BYTES);

    __half *disp = nullptr, *h = nullptr, *w1h = nullptr, *w2h = nullptr;
    float *y = nullptr;
    cudaGetSymbolAddress((void**)&disp, g_disp);
    cudaGetSymbolAddress((void**)&h, g_h);
    cudaGetSymbolAddress((void**)&y, g_y);
    cudaGetSymbolAddress((void**)&w1h, g_W1h);
    cudaGetSymbolAddress((void**)&w2h, g_W2h);

    init_kernel<<<1, 32>>>();

    // transpose + fp16 convert weights: W1 [C][F]->[F][C], W2 [F][C]->[C][F]
    {
        dim3 blk(32, 8);
        dim3 t1(F_DIM / 32, C_DIM / 32, E_NUM);
        transpose_h_kernel<<<t1, blk>>>(W1, w1h, C_DIM, F_DIM);
        dim3 t2(C_DIM / 32, F_DIM / 32, E_NUM);
        transpose_h_kernel<<<t2, blk>>>(W2, w2h, F_DIM, C_DIM);
    }

    gate_kernel<<<N_TOK / 8, 256>>>(x, w_gate, b_gate);
    scan_kernel<<<1, 256>>>(out, out_size);
    dispatch_kernel<<<S_SLOTS, 128>>>(x);

    {
        dim3 grid1(F_DIM / GBN, CAP / GBM, E_NUM);
        gemm_kernel<true, __half><<<grid1, 256, GEMM_SMEM_BYTES>>>(disp, w1h, b1, h, CAP, F_DIM, C_DIM);

        dim3 grid2(C_DIM / GBN, CAP / GBM, E_NUM);
        gemm_kernel<false, float><<<grid2, 256, GEMM_SMEM_BYTES>>>(h, w2h, b2, y, CAP, C_DIM, F_DIM);
    }

    combine_kernel<<<N_TOK, 128>>>(out);
}